// round 16
// baseline (speedup 1.0000x reference)
#include <cuda_runtime.h>
#include <math.h>

// NTXentLoss: B=2048, P=16, N=128, D=512 (fp32).
// R16: R14 base (best: 55.36us) + 3-stage pipeline:
//      stage 0: prefetch.global.L2 of row i+16 (lanes 0-15, one 128B line each)
//      stage 1: register load of row i+8 (R8 prefetch)
//      stage 2: compute row i
//      Converts the per-row DRAM miss (~577cyc) into an L2 hit (~234cyc).

#define DDIM 512
#define D4 (DDIM / 4)
#define THREADS 256
#define NWARPS (THREADS / 32)   // 8
#define TEMP_INV 10.0f
#define COS_EPS 1e-8f

// scratch (no cudaMalloc allowed)
__device__ float g_loss[4096];
__device__ unsigned int g_count = 0;

__device__ __forceinline__ void prefetch_l2(const void* p) {
    asm volatile("prefetch.global.L2 [%0];" :: "l"(p));
}

__device__ __forceinline__ float warpReduceSum(float v) {
#pragma unroll
    for (int o = 16; o; o >>= 1) v += __shfl_down_sync(0xffffffffu, v, o);
    return v;
}

__device__ __forceinline__ float warpAllSum(float v) {
#pragma unroll
    for (int o = 16; o; o >>= 1) v += __shfl_xor_sync(0xffffffffu, v, o);
    return v;
}

__device__ __forceinline__ float warpAllMax(float v) {
#pragma unroll
    for (int o = 16; o; o >>= 1) v = fmaxf(v, __shfl_xor_sync(0xffffffffu, v, o));
    return v;
}

__global__ void __launch_bounds__(THREADS, 5)
ntxent_main_kernel(const float* __restrict__ target,
                   const float* __restrict__ positives,
                   const float* __restrict__ negatives,
                   const int* __restrict__ pos_idx,
                   const int* __restrict__ neg_mask,
                   float* __restrict__ out,
                   int B, int P, int N) {
    const int b = blockIdx.x;
    const int tid = threadIdx.x;
    const int lane = tid & 31;
    const int w = tid >> 5;

    __shared__ float4 s_tgt[D4];      // 2KB target row
    __shared__ float s_dot[132];      // full row dots: [0..M-1]=negs, [M]=pos
    __shared__ float s_q[132];        // full row squared norms
    __shared__ int   s_valid[132];
    __shared__ int   s_wcnt[NWARPS];

    // --- compact valid negative indices (deterministic prefix via ballot) ---
    int mvalid = 0;
    if (tid < N) mvalid = (neg_mask[(size_t)b * N + tid] != 0);
    unsigned bal = __ballot_sync(0xffffffffu, mvalid);
    if (lane == 0) s_wcnt[w] = __popc(bal);

    // --- target row -> SMEM ---
    if (tid < D4) {
        s_tgt[tid] = ((const float4*)(target + (size_t)b * DDIM))[tid];
    }
    const int pi = pos_idx[b];
    __syncthreads();   // s_tgt + s_wcnt ready

    int off = 0, M = 0;
#pragma unroll
    for (int j = 0; j < NWARPS; j++) {
        int c = s_wcnt[j];
        if (j < w) off += c;
        M += c;
    }
    if (mvalid) s_valid[off + __popc(bal & ((1u << lane) - 1u))] = tid;
    __syncthreads();   // s_valid ready

    // --- 3-stage pipelined row streaming ---
    const float4* negb = (const float4*)(negatives + (size_t)b * (size_t)N * DDIM);
    const float4* posr = (const float4*)(positives + ((size_t)b * P + pi) * (size_t)DDIM);
    const int R = M + 1;

    int i = w;
    if (i < R) {
        const float4* vc = (i < M) ? (negb + (size_t)s_valid[i] * D4) : posr;
        float4 cur[4];
#pragma unroll
        for (int k = 0; k < 4; k++) cur[k] = vc[lane + 32 * k];

        // prefetch row i+8 target-of-register-load's successor (i+16)
        {
            const int p2 = i + 2 * NWARPS;
            if (p2 < R && lane < 16) {
                const float4* vp = (p2 < M) ? (negb + (size_t)s_valid[p2] * D4) : posr;
                prefetch_l2((const char*)vp + lane * 128);
            }
        }

        for (; i < R; i += NWARPS) {
            // stage 1: register-load row i+8
            const int j = i + NWARPS;
            const float4* vn = (j < R) ? ((j < M) ? (negb + (size_t)s_valid[j] * D4) : posr)
                                       : vc;
            float4 nxt[4];
#pragma unroll
            for (int k = 0; k < 4; k++) nxt[k] = vn[lane + 32 * k];

            // stage 0: L2-prefetch row i+24 (consumed 2 iterations later)
            const int p2 = i + 3 * NWARPS;
            if (p2 < R && lane < 16) {
                const float4* vp = (p2 < M) ? (negb + (size_t)s_valid[p2] * D4) : posr;
                prefetch_l2((const char*)vp + lane * 128);
            }

            // stage 2: compute row i
            float dot = 0.0f, q = 0.0f;
#pragma unroll
            for (int k = 0; k < 4; k++) {
                float4 t = s_tgt[lane + 32 * k];
                dot = fmaf(cur[k].x, t.x, dot); dot = fmaf(cur[k].y, t.y, dot);
                dot = fmaf(cur[k].z, t.z, dot); dot = fmaf(cur[k].w, t.w, dot);
                q = fmaf(cur[k].x, cur[k].x, q); q = fmaf(cur[k].y, cur[k].y, q);
                q = fmaf(cur[k].z, cur[k].z, q); q = fmaf(cur[k].w, cur[k].w, q);
            }
            dot = warpReduceSum(dot);
            q = warpReduceSum(q);
            if (lane == 0) { s_dot[i] = dot; s_q[i] = q; }

#pragma unroll
            for (int k = 0; k < 4; k++) cur[k] = nxt[k];
            vc = vn;
        }
    }
    __syncthreads();   // ONLY epilogue barrier

    // --- single-warp epilogue (two-pass, no register array) ---
    if (w == 0) {
        float tq = 0.0f;
#pragma unroll
        for (int k = 0; k < 4; k++) {
            float4 t = s_tgt[lane + 32 * k];
            tq = fmaf(t.x, t.x, tq); tq = fmaf(t.y, t.y, tq);
            tq = fmaf(t.z, t.z, tq); tq = fmaf(t.w, t.w, tq);
        }
        const float tnorm = sqrtf(warpAllSum(tq));

        float mx = -INFINITY;
        for (int r = lane; r < R; r += 32) {
            float sim = (s_dot[r] / fmaxf(sqrtf(s_q[r]) * tnorm, COS_EPS)) * TEMP_INV;
            s_dot[r] = sim;
            mx = fmaxf(mx, sim);
        }
        __syncwarp();
        mx = warpAllMax(mx);

        float e = 0.0f;
        for (int r = lane; r < R; r += 32) e += expf(s_dot[r] - mx);
        e = warpAllSum(e);
        const float pos_sim = s_dot[M];

        int islast = 0;
        if (lane == 0) {
            g_loss[b] = logf(e) + mx - pos_sim;
            __threadfence();
            unsigned int old = atomicAdd(&g_count, 1u);
            islast = (old == (unsigned int)(B - 1));
        }
        islast = __shfl_sync(0xffffffffu, islast, 0);
        if (islast) {
            __threadfence();
            float v = 0.0f;
            for (int k = lane; k < B; k += 32) v += g_loss[k];
            v = warpAllSum(v);
            if (lane == 0) {
                out[0] = v / (float)B;
                g_count = 0;  // reset for next graph replay
            }
        }
    }
}

extern "C" void kernel_launch(void* const* d_in, const int* in_sizes, int n_in,
                              void* d_out, int out_size) {
    const float* target = (const float*)d_in[0];
    const float* positives = (const float*)d_in[1];
    const float* negatives = (const float*)d_in[2];
    const int* pos_idx = (const int*)d_in[3];
    const int* neg_mask = (const int*)d_in[4];
    float* out = (float*)d_out;

    const int B = in_sizes[0] / DDIM;                 // 2048
    const int P = in_sizes[1] / in_sizes[0];          // 16
    const int N = in_sizes[2] / in_sizes[0];          // 128

    ntxent_main_kernel<<<B, THREADS>>>(target, positives, negatives, pos_idx,
                                       neg_mask, out, B, P, N);
}

// round 17
// speedup vs baseline: 1.1527x; 1.1527x over previous
#include <cuda_runtime.h>
#include <math.h>

// NTXentLoss: B=2048, P=16, N=128, D=512 (fp32).
// R17: R14 base (best) + DRAM page-locality row assignment:
//   - warps take CONTIGUOUS chunks of the compacted valid-row list (successive
//     fetches by one warp are adjacent in memory -> DRAM row-buffer hits)
//     instead of stride-8 interleave (16KB jumps).
//   - __ldcs (evict-first) streaming loads for the 512MB negatives pass.

#define DDIM 512
#define D4 (DDIM / 4)
#define THREADS 256
#define NWARPS (THREADS / 32)   // 8
#define TEMP_INV 10.0f
#define COS_EPS 1e-8f

// scratch (no cudaMalloc allowed)
__device__ float g_loss[4096];
__device__ unsigned int g_count = 0;

__device__ __forceinline__ float4 ldcs4(const float4* p) {
    return __ldcs(p);
}

__device__ __forceinline__ float warpReduceSum(float v) {
#pragma unroll
    for (int o = 16; o; o >>= 1) v += __shfl_down_sync(0xffffffffu, v, o);
    return v;
}

__device__ __forceinline__ float warpAllSum(float v) {
#pragma unroll
    for (int o = 16; o; o >>= 1) v += __shfl_xor_sync(0xffffffffu, v, o);
    return v;
}

__device__ __forceinline__ float warpAllMax(float v) {
#pragma unroll
    for (int o = 16; o; o >>= 1) v = fmaxf(v, __shfl_xor_sync(0xffffffffu, v, o));
    return v;
}

__global__ void __launch_bounds__(THREADS, 5)
ntxent_main_kernel(const float* __restrict__ target,
                   const float* __restrict__ positives,
                   const float* __restrict__ negatives,
                   const int* __restrict__ pos_idx,
                   const int* __restrict__ neg_mask,
                   float* __restrict__ out,
                   int B, int P, int N) {
    const int b = blockIdx.x;
    const int tid = threadIdx.x;
    const int lane = tid & 31;
    const int w = tid >> 5;

    __shared__ float4 s_tgt[D4];      // 2KB target row
    __shared__ float s_dot[132];      // full row dots: [0..M-1]=negs, [M]=pos
    __shared__ float s_q[132];        // full row squared norms
    __shared__ int   s_valid[132];
    __shared__ int   s_wcnt[NWARPS];

    // --- compact valid negative indices (deterministic prefix via ballot) ---
    int mvalid = 0;
    if (tid < N) mvalid = (neg_mask[(size_t)b * N + tid] != 0);
    unsigned bal = __ballot_sync(0xffffffffu, mvalid);
    if (lane == 0) s_wcnt[w] = __popc(bal);

    // --- target row -> SMEM ---
    if (tid < D4) {
        s_tgt[tid] = ((const float4*)(target + (size_t)b * DDIM))[tid];
    }
    const int pi = pos_idx[b];
    __syncthreads();   // s_tgt + s_wcnt ready

    int off = 0, M = 0;
#pragma unroll
    for (int j = 0; j < NWARPS; j++) {
        int c = s_wcnt[j];
        if (j < w) off += c;
        M += c;
    }
    if (mvalid) s_valid[off + __popc(bal & ((1u << lane) - 1u))] = tid;
    __syncthreads();   // s_valid ready

    // --- software-pipelined streaming over a CONTIGUOUS chunk of rows ---
    const float4* negb = (const float4*)(negatives + (size_t)b * (size_t)N * DDIM);
    const float4* posr = (const float4*)(positives + ((size_t)b * P + pi) * (size_t)DDIM);
    const int R = M + 1;

    // warp w owns rows [beg, end): contiguous in the compacted (ascending)
    // list -> successive DRAM fetches by this warp are adjacent rows.
    const int chunk = (R + NWARPS - 1) / NWARPS;
    const int beg = w * chunk;
    const int end = (beg + chunk < R) ? (beg + chunk) : R;

    int i = beg;
    if (i < end) {
        const float4* vc = (i < M) ? (negb + (size_t)s_valid[i] * D4) : posr;
        float4 cur[4];
#pragma unroll
        for (int k = 0; k < 4; k++) cur[k] = ldcs4(&vc[lane + 32 * k]);

        for (; i < end; i++) {
            const int j = i + 1;
            const float4* vn = (j < end) ? ((j < M) ? (negb + (size_t)s_valid[j] * D4) : posr)
                                         : vc;
            float4 nxt[4];
#pragma unroll
            for (int k = 0; k < 4; k++) nxt[k] = ldcs4(&vn[lane + 32 * k]);

            float dot = 0.0f, q = 0.0f;
#pragma unroll
            for (int k = 0; k < 4; k++) {
                float4 t = s_tgt[lane + 32 * k];
                dot = fmaf(cur[k].x, t.x, dot); dot = fmaf(cur[k].y, t.y, dot);
                dot = fmaf(cur[k].z, t.z, dot); dot = fmaf(cur[k].w, t.w, dot);
                q = fmaf(cur[k].x, cur[k].x, q); q = fmaf(cur[k].y, cur[k].y, q);
                q = fmaf(cur[k].z, cur[k].z, q); q = fmaf(cur[k].w, cur[k].w, q);
            }
            dot = warpReduceSum(dot);
            q = warpReduceSum(q);
            if (lane == 0) { s_dot[i] = dot; s_q[i] = q; }

#pragma unroll
            for (int k = 0; k < 4; k++) cur[k] = nxt[k];
            vc = vn;
        }
    }
    __syncthreads();   // ONLY epilogue barrier

    // --- single-warp epilogue (two-pass) ---
    if (w == 0) {
        float tq = 0.0f;
#pragma unroll
        for (int k = 0; k < 4; k++) {
            float4 t = s_tgt[lane + 32 * k];
            tq = fmaf(t.x, t.x, tq); tq = fmaf(t.y, t.y, tq);
            tq = fmaf(t.z, t.z, tq); tq = fmaf(t.w, t.w, tq);
        }
        const float tnorm = sqrtf(warpAllSum(tq));

        float mx = -INFINITY;
        for (int r = lane; r < R; r += 32) {
            float sim = (s_dot[r] / fmaxf(sqrtf(s_q[r]) * tnorm, COS_EPS)) * TEMP_INV;
            s_dot[r] = sim;
            mx = fmaxf(mx, sim);
        }
        __syncwarp();
        mx = warpAllMax(mx);

        float e = 0.0f;
        for (int r = lane; r < R; r += 32) e += expf(s_dot[r] - mx);
        e = warpAllSum(e);
        const float pos_sim = s_dot[M];

        int islast = 0;
        if (lane == 0) {
            g_loss[b] = logf(e) + mx - pos_sim;
            __threadfence();
            unsigned int old = atomicAdd(&g_count, 1u);
            islast = (old == (unsigned int)(B - 1));
        }
        islast = __shfl_sync(0xffffffffu, islast, 0);
        if (islast) {
            __threadfence();
            float v = 0.0f;
            for (int k = lane; k < B; k += 32) v += g_loss[k];
            v = warpAllSum(v);
            if (lane == 0) {
                out[0] = v / (float)B;
                g_count = 0;  // reset for next graph replay
            }
        }
    }
}

extern "C" void kernel_launch(void* const* d_in, const int* in_sizes, int n_in,
                              void* d_out, int out_size) {
    const float* target = (const float*)d_in[0];
    const float* positives = (const float*)d_in[1];
    const float* negatives = (const float*)d_in[2];
    const int* pos_idx = (const int*)d_in[3];
    const int* neg_mask = (const int*)d_in[4];
    float* out = (float*)d_out;

    const int B = in_sizes[0] / DDIM;                 // 2048
    const int P = in_sizes[1] / in_sizes[0];          // 16
    const int N = in_sizes[2] / in_sizes[0];          // 128

    ntxent_main_kernel<<<B, THREADS>>>(target, positives, negatives, pos_idx,
                                       neg_mask, out, B, P, N);
}